// round 11
// baseline (speedup 1.0000x reference)
#include <cuda_runtime.h>
#include <math.h>

#define N_ENT 100000
#define N_REL 64
#define EDIM  64
#define KN    32
#define BSZ   1024
#define SLOPE 0.2f

__device__ float g_scale[N_ENT];
__device__ __align__(16) float g_Rw[N_REL * EDIM];  // [r][f] rows

// ---- packed fp32x2 helpers ----
__device__ __forceinline__ unsigned long long fma2(unsigned long long a,
                                                   unsigned long long b,
                                                   unsigned long long c) {
    unsigned long long d;
    asm("fma.rn.f32x2 %0, %1, %2, %3;" : "=l"(d) : "l"(a), "l"(b), "l"(c));
    return d;
}
__device__ __forceinline__ unsigned long long pack2(float lo, float hi) {
    unsigned long long d;
    asm("mov.b64 %0, {%1, %2};" : "=l"(d) : "f"(lo), "f"(hi));
    return d;
}
__device__ __forceinline__ float2 unpack2(unsigned long long v) {
    float2 r;
    asm("mov.b64 {%0, %1}, %2;" : "=f"(r.x), "=f"(r.y) : "l"(v));
    return r;
}

// ---------------------------------------------------------------------------
// Prep: per-row E scale (782 blocks) + Rw slices (16 blocks, [r][f] out)
// ---------------------------------------------------------------------------
__global__ void prep_kernel(const float* __restrict__ E,
                            const float* __restrict__ R,
                            const float* __restrict__ att_w1) {
    const int tid = threadIdx.x;  // 256
    if (blockIdx.x < 782) {
        const int row  = blockIdx.x * 128 + (tid >> 1);
        const int part = tid & 1;
        if (row >= N_ENT) return;
        const float4* Ev = reinterpret_cast<const float4*>(E + row * 64) + part * 8;
        float ss = 0.f;
        #pragma unroll
        for (int i = 0; i < 8; i++) {
            float4 v = Ev[i];
            ss += v.x*v.x + v.y*v.y + v.z*v.z + v.w*v.w;
        }
        ss += __shfl_xor_sync(0xffffffffu, ss, 1, 2);
        if (part == 0) {
            float n = sqrtf(ss);
            g_scale[row] = (n > 1.0f) ? (1.0f / (n + 1e-7f)) : 1.0f;
        }
        return;
    }
    __shared__ __align__(16) float sRn[N_REL * EDIM];
    __shared__ float sScale[N_REL];
    const int slice = blockIdx.x - 782;
    for (int i = tid; i < N_REL * EDIM; i += 256) sRn[i] = R[i];
    __syncthreads();
    if (tid < N_REL) {
        const float4* rv = reinterpret_cast<const float4*>(sRn + tid * EDIM);
        float ss = 0.f;
        #pragma unroll
        for (int e4 = 0; e4 < 16; e4++) {
            float4 v = rv[e4];
            ss += v.x*v.x + v.y*v.y + v.z*v.z + v.w*v.w;
        }
        float n = sqrtf(ss);
        sScale[tid] = (n > 1.0f) ? (1.0f / (n + 1e-7f)) : 1.0f;
    }
    __syncthreads();
    for (int i = tid; i < N_REL * EDIM; i += 256) sRn[i] *= sScale[i >> 6];
    __syncthreads();
    {
        int i = slice * 256 + tid;       // g_Rw[r][f]
        int r = i >> 6, f = i & 63;
        const float4* w  = reinterpret_cast<const float4*>(att_w1 + f * 128 + 64);
        const float4* rn = reinterpret_cast<const float4*>(sRn + r * 64);
        float a0 = 0.f, a1 = 0.f;
        #pragma unroll
        for (int e4 = 0; e4 < 16; e4 += 2) {
            float4 rv = rn[e4],     wv = w[e4];
            float4 rw = rn[e4 + 1], ww = w[e4 + 1];
            a0 += rv.x*wv.x + rv.y*wv.y + rv.z*wv.z + rv.w*wv.w;
            a1 += rw.x*ww.x + rw.y*ww.y + rw.z*ww.z + rw.w*ww.w;
        }
        g_Rw[i] = a0 + a1;
    }
}

// ---------------------------------------------------------------------------
// Main: one block per batch element, 192 threads, 6 blocks/SM.
// Stage-7 uses a 4-way feature split (hidp = 16 regs) to fit 56 regs.
// ---------------------------------------------------------------------------
__global__ __launch_bounds__(192, 6) void kgan_main_kernel(
    const int*   __restrict__ entity_idx,
    const int*   __restrict__ adj_entity,
    const int*   __restrict__ adj_relation,
    const float* __restrict__ E,
    const float* __restrict__ att_w1,
    const float* __restrict__ att_w2,
    const float* __restrict__ att_w3,
    const float* __restrict__ wx_w,
    const float* __restrict__ wx_b,
    const float* __restrict__ wc_w,
    const float* __restrict__ wc_b,
    float*       __restrict__ out)
{
    __shared__ __align__(16) float sW2[64 * 64];    // permuted float4 slots: g*16 + j*4 + fq
    __shared__ __align__(16) int   sPacked[1024];   // ei | (ri<<17)
    __shared__ __align__(16) float sWt[1024];       // pair weights; warp tails reused for partials
    __shared__ float sw3[64];
    __shared__ float sh[64], shsum[64], sbh1[64], sbh2[64];
    __shared__ int   sEnt1[32], sRel1[32];
    __shared__ float sScale1[32];
    __shared__ float sA[96];
    __shared__ float sWk[32], sWks[32], sE2[64];
    __shared__ float sDen[6];
    __shared__ float sAgg1[64], sAgg2[64], sV1[64], sV2[64];

    const int tid  = threadIdx.x;
    const int b    = blockIdx.x;
    const int lane = tid & 31;
    const int warp = tid >> 5;

    // ================= phase A: W2 table (4-way permute) + indices =========
    {
        const float4* Ws = reinterpret_cast<const float4*>(att_w2);
        float4*       Wd = reinterpret_cast<float4*>(sW2);
        for (int i = tid; i < 1024; i += 192) {
            int g = i >> 4, i4 = i & 15;
            // src float4 i4 = features [4*i4, 4*i4+4): quarter fq=i4>>2, j=i4&3
            Wd[g * 16 + ((i4 & 3) << 2) + (i4 >> 2)] = Ws[i];
        }
    }
    if (tid < 64) sw3[tid] = att_w3[tid];
    const int eidx = entity_idx[b];
    if (tid < 32) {
        int e1 = adj_entity[eidx * KN + tid];
        sEnt1[tid]   = e1;
        sRel1[tid]   = adj_relation[eidx * KN + tid];
        sScale1[tid] = g_scale[e1];
    }
    if (tid < 64) sh[tid] = E[eidx * 64 + tid] * g_scale[eidx];
    __syncthreads();

    // ====== phase B (concurrent): hsum (warps 0-1) | pair staging (2-5) ====
    if (tid < 64) {
        float s = 0.f;
        #pragma unroll 8
        for (int k = 0; k < 32; k++)
            s += sScale1[k] * E[sEnt1[k] * 64 + tid];
        shsum[tid] = s;
    } else {
        const int t = tid - 64;           // 0..127
        #pragma unroll
        for (int q = 0; q < 8; q++) {
            int p  = t + q * 128;
            int n1 = p >> 5, k = p & 31;
            int base = sEnt1[n1] * KN;
            int ei = adj_entity[base + k];
            int ri = adj_relation[base + k];
            sPacked[p] = ei | (ri << 17);
        }
    }
    __syncthreads();

    // ====== phase C: bh1 = h @ w1h^T, bh2 = hsum @ w1h^T (warps 0-3) =======
    if (tid < 128) {
        int f = tid & 63;
        const float*  src = (tid < 64) ? sh : shsum;
        const float4* w   = reinterpret_cast<const float4*>(att_w1 + f * 128);
        float a0 = 0.f, a1 = 0.f;
        #pragma unroll
        for (int e4 = 0; e4 < 16; e4 += 2) {
            float4 wv = w[e4], ww = w[e4 + 1];
            a0 += wv.x * src[e4*4]   + wv.y * src[e4*4+1]
                + wv.z * src[e4*4+2] + wv.w * src[e4*4+3];
            a1 += ww.x * src[e4*4+4] + ww.y * src[e4*4+5]
                + ww.z * src[e4*4+6] + ww.w * src[e4*4+7];
        }
        if (tid < 64) sbh1[f] = a0 + a1; else sbh2[f] = a0 + a1;
    }
    __syncthreads();

    // ====== stage 7: 96 tasks x 4 f-quarters = 384 thread-tasks, 2 passes ==
    #pragma unroll
    for (int pass = 0; pass < 2; pass++) {
        const int tt   = tid + pass * 192;   // 0..383, exact
        const int task = tt >> 2;
        const int fq   = tt & 3;
        const float* bh = (task < 32) ? sbh1 : sbh2;
        const int    r  = (task < 32) ? sRel1[task] : (task - 32);

        // hidden quarter: features [fq*16, fq*16+16) packed as 8 x f32x2
        const float4* rw = reinterpret_cast<const float4*>(g_Rw + r * 64) + fq * 4;
        unsigned long long hidp[8];
        #pragma unroll
        for (int m = 0; m < 4; m++) {
            float4 rv = __ldg(&rw[m]);
            int f = fq * 16 + m * 4;
            float h0 = fmaxf(bh[f]     + rv.x, 0.0f);
            float h1 = fmaxf(bh[f + 1] + rv.y, 0.0f);
            float h2 = fmaxf(bh[f + 2] + rv.z, 0.0f);
            float h3 = fmaxf(bh[f + 3] + rv.w, 0.0f);
            hidp[m * 2]     = pack2(h0, h1);
            hidp[m * 2 + 1] = pack2(h2, h3);
        }
        const ulonglong2* w2 = reinterpret_cast<const ulonglong2*>(sW2);
        float a = 0.0f;
        #pragma unroll
        for (int gb = 0; gb < 64; gb += 8) {
            float dp[8];
            #pragma unroll
            for (int u = 0; u < 8; u++) {
                const int g = gb + u;
                unsigned long long dpp = 0ull;
                #pragma unroll
                for (int j = 0; j < 4; j++) {
                    ulonglong2 wv = w2[g * 16 + j * 4 + fq];
                    dpp = fma2(wv.x, hidp[j * 2],     dpp);
                    dpp = fma2(wv.y, hidp[j * 2 + 1], dpp);
                }
                float2 dd = unpack2(dpp);
                dp[u] = dd.x + dd.y;
            }
            #pragma unroll
            for (int u = 0; u < 8; u++) {
                dp[u] += __shfl_xor_sync(0xffffffffu, dp[u], 1);
                dp[u] += __shfl_xor_sync(0xffffffffu, dp[u], 2);
            }
            #pragma unroll
            for (int u = 0; u < 8; u++)
                a += sw3[gb + u] * fmaxf(dp[u], 0.0f);
        }
        if (fq == 0) sA[task] = a;
    }
    __syncthreads();

    // ====== exp(sigmoid(a)) tables =========================================
    if (tid < 96) {
        float e = __expf(1.0f / (1.0f + __expf(-sA[tid])));
        if (tid < 32) { sWk[tid] = e; sWks[tid] = e * sScale1[tid]; }
        else          sE2[tid - 32] = e;
    }
    __syncthreads();

    // ====== hop-2 pair weights + denominator (all 6 warps) =================
    {
        float esum = 0.f;
        for (int p = tid; p < 1024; p += 192) {
            int pk = sPacked[p];
            int ei = pk & 0x1FFFF;
            float e = sE2[pk >> 17];
            esum  += e;
            sWt[p] = e * g_scale[ei];
        }
        #pragma unroll
        for (int o = 16; o > 0; o >>= 1) esum += __shfl_xor_sync(0xffffffffu, esum, o);
        if (lane == 0) sDen[warp] = esum;
    }
    __syncthreads();

    // ====== gather (warps 0-3) | hop-1 aggregation (warps 4-5) =============
    if (warp < 4) {
        float accx = 0.f, accy = 0.f;
        const float2* E2 = reinterpret_cast<const float2*>(E);
        const int pbase = warp * 256;
        #pragma unroll 8
        for (int t = 0; t < 256; t++) {
            int   pk = sPacked[pbase + t];   // broadcast LDS
            float wt = sWt[pbase + t];       // broadcast LDS
            int  idx = pk & 0x1FFFF;
            float2 v = E2[idx * 32 + lane];
            accx += wt * v.x;
            accy += wt * v.y;
        }
        // partials into this warp's own fully-consumed sWt segment
        sWt[pbase + lane * 2]     = accx;    // feature 2*lane
        sWt[pbase + lane * 2 + 1] = accy;    // feature 2*lane+1
    } else {
        const int t = tid - 128;             // 0..63
        float s1 = 0.f, acc = 0.f;
        #pragma unroll
        for (int k = 0; k < 32; k++) s1 += sWk[k];
        #pragma unroll 8
        for (int k = 0; k < 32; k++)
            acc += sWks[k] * E[sEnt1[k] * 64 + t];
        sAgg1[t] = acc / s1;
    }
    __syncthreads();

    // ====== hop-2 combine ==================================================
    if (tid < 64) {
        float s2 = sDen[0] + sDen[1] + sDen[2] + sDen[3] + sDen[4] + sDen[5];
        float acc = sWt[tid] + sWt[256 + tid] + sWt[512 + tid] + sWt[768 + tid];
        sAgg2[tid] = acc / s2;
    }
    __syncthreads();

    // ====== v1/v2 = leaky(agg @ wx_w^T + wx_b) =============================
    if (tid < 64) {
        const float4* w = reinterpret_cast<const float4*>(wx_w + tid * 64);
        float a1 = wx_b[tid], a2 = a1;
        #pragma unroll
        for (int e4 = 0; e4 < 16; e4++) {
            float4 wv = w[e4];
            a1 += wv.x * sAgg1[e4*4]   + wv.y * sAgg1[e4*4+1]
                + wv.z * sAgg1[e4*4+2] + wv.w * sAgg1[e4*4+3];
            a2 += wv.x * sAgg2[e4*4]   + wv.y * sAgg2[e4*4+1]
                + wv.z * sAgg2[e4*4+2] + wv.w * sAgg2[e4*4+3];
        }
        sV1[tid] = (a1 >= 0.f) ? a1 : SLOPE * a1;
        sV2[tid] = (a2 >= 0.f) ? a2 : SLOPE * a2;
    }
    __syncthreads();

    // ====== emb1/emb2 = leaky([x, v] @ wc_w^T + wc_b) + h out ==============
    if (tid < 64) {
        const float4* w = reinterpret_cast<const float4*>(wc_w + tid * 128);
        float a1 = wc_b[tid], a2 = a1;
        #pragma unroll
        for (int e4 = 0; e4 < 16; e4++) {
            float4 wv = w[e4];
            a1 += wv.x * sh[e4*4]      + wv.y * sh[e4*4+1]
                + wv.z * sh[e4*4+2]    + wv.w * sh[e4*4+3];
            a2 += wv.x * shsum[e4*4]   + wv.y * shsum[e4*4+1]
                + wv.z * shsum[e4*4+2] + wv.w * shsum[e4*4+3];
        }
        #pragma unroll
        for (int e4 = 0; e4 < 16; e4++) {
            float4 wv = w[16 + e4];
            a1 += wv.x * sV1[e4*4]   + wv.y * sV1[e4*4+1]
                + wv.z * sV1[e4*4+2] + wv.w * sV1[e4*4+3];
            a2 += wv.x * sV2[e4*4]   + wv.y * sV2[e4*4+1]
                + wv.z * sV2[e4*4+2] + wv.w * sV2[e4*4+3];
        }
        out[b * 192 + 64 + tid]  = (a1 >= 0.f) ? a1 : SLOPE * a1;
        out[b * 192 + tid]       = (a2 >= 0.f) ? a2 : SLOPE * a2;
        out[b * 192 + 128 + tid] = sh[tid];
    }
}

extern "C" void kernel_launch(void* const* d_in, const int* in_sizes, int n_in,
                              void* d_out, int out_size) {
    const int*   entity_idx   = (const int*)  d_in[0];
    const int*   adj_entity   = (const int*)  d_in[1];
    const int*   adj_relation = (const int*)  d_in[2];
    const float* E            = (const float*)d_in[3];
    const float* R            = (const float*)d_in[4];
    const float* att_w1       = (const float*)d_in[5];
    const float* att_w2       = (const float*)d_in[6];
    const float* att_w3       = (const float*)d_in[7];
    const float* wx_w         = (const float*)d_in[8];
    const float* wx_b         = (const float*)d_in[9];
    const float* wc_w         = (const float*)d_in[10];
    const float* wc_b         = (const float*)d_in[11];
    float* out = (float*)d_out;

    prep_kernel<<<798, 256>>>(E, R, att_w1);
    kgan_main_kernel<<<BSZ, 192>>>(entity_idx, adj_entity, adj_relation, E,
                                   att_w1, att_w2, att_w3,
                                   wx_w, wx_b, wc_w, wc_b, out);
}

// round 12
// speedup vs baseline: 1.2077x; 1.2077x over previous
#include <cuda_runtime.h>
#include <math.h>

#define N_ENT 100000
#define N_REL 64
#define EDIM  64
#define KN    32
#define BSZ   1024
#define SLOPE 0.2f

__device__ float g_scale[N_ENT];
__device__ __align__(16) float g_Rw[N_REL * EDIM];  // [r][f] rows

// ---- packed fp32x2 helpers ----
__device__ __forceinline__ unsigned long long fma2(unsigned long long a,
                                                   unsigned long long b,
                                                   unsigned long long c) {
    unsigned long long d;
    asm("fma.rn.f32x2 %0, %1, %2, %3;" : "=l"(d) : "l"(a), "l"(b), "l"(c));
    return d;
}
__device__ __forceinline__ unsigned long long pack2(float lo, float hi) {
    unsigned long long d;
    asm("mov.b64 %0, {%1, %2};" : "=l"(d) : "f"(lo), "f"(hi));
    return d;
}
__device__ __forceinline__ float2 unpack2(unsigned long long v) {
    float2 r;
    asm("mov.b64 {%0, %1}, %2;" : "=f"(r.x), "=f"(r.y) : "l"(v));
    return r;
}

// ---------------------------------------------------------------------------
// Prep: per-row E scale (782 blocks) + Rw slices (16 blocks, [r][f] out)
// ---------------------------------------------------------------------------
__global__ void prep_kernel(const float* __restrict__ E,
                            const float* __restrict__ R,
                            const float* __restrict__ att_w1) {
    const int tid = threadIdx.x;  // 256
    if (blockIdx.x < 782) {
        const int row  = blockIdx.x * 128 + (tid >> 1);
        const int part = tid & 1;
        if (row >= N_ENT) return;
        const float4* Ev = reinterpret_cast<const float4*>(E + row * 64) + part * 8;
        float ss = 0.f;
        #pragma unroll
        for (int i = 0; i < 8; i++) {
            float4 v = Ev[i];
            ss += v.x*v.x + v.y*v.y + v.z*v.z + v.w*v.w;
        }
        ss += __shfl_xor_sync(0xffffffffu, ss, 1, 2);
        if (part == 0) {
            float n = sqrtf(ss);
            g_scale[row] = (n > 1.0f) ? (1.0f / (n + 1e-7f)) : 1.0f;
        }
        return;
    }
    __shared__ __align__(16) float sRn[N_REL * EDIM];
    __shared__ float sScale[N_REL];
    const int slice = blockIdx.x - 782;
    for (int i = tid; i < N_REL * EDIM; i += 256) sRn[i] = R[i];
    __syncthreads();
    if (tid < N_REL) {
        const float4* rv = reinterpret_cast<const float4*>(sRn + tid * EDIM);
        float ss = 0.f;
        #pragma unroll
        for (int e4 = 0; e4 < 16; e4++) {
            float4 v = rv[e4];
            ss += v.x*v.x + v.y*v.y + v.z*v.z + v.w*v.w;
        }
        float n = sqrtf(ss);
        sScale[tid] = (n > 1.0f) ? (1.0f / (n + 1e-7f)) : 1.0f;
    }
    __syncthreads();
    for (int i = tid; i < N_REL * EDIM; i += 256) sRn[i] *= sScale[i >> 6];
    __syncthreads();
    {
        int i = slice * 256 + tid;       // g_Rw[r][f]
        int r = i >> 6, f = i & 63;
        const float4* w  = reinterpret_cast<const float4*>(att_w1 + f * 128 + 64);
        const float4* rn = reinterpret_cast<const float4*>(sRn + r * 64);
        float a0 = 0.f, a1 = 0.f;
        #pragma unroll
        for (int e4 = 0; e4 < 16; e4 += 2) {
            float4 rv = rn[e4],     wv = w[e4];
            float4 rw = rn[e4 + 1], ww = w[e4 + 1];
            a0 += rv.x*wv.x + rv.y*wv.y + rv.z*wv.z + rv.w*wv.w;
            a1 += rw.x*ww.x + rw.y*ww.y + rw.z*ww.z + rw.w*ww.w;
        }
        g_Rw[i] = a0 + a1;
    }
}

// ---------------------------------------------------------------------------
// Main: one block per batch element, 192 threads, 5 blocks/SM.
// Stage-7 = register-tiled GEMM over hid[48][68] in shared (2 halves),
// W2 stored transposed [f][g]. hid aliases the pair-staging buffers.
// ---------------------------------------------------------------------------
__global__ __launch_bounds__(192, 5) void kgan_main_kernel(
    const int*   __restrict__ entity_idx,
    const int*   __restrict__ adj_entity,
    const int*   __restrict__ adj_relation,
    const float* __restrict__ E,
    const float* __restrict__ att_w1,
    const float* __restrict__ att_w2,
    const float* __restrict__ att_w3,
    const float* __restrict__ wx_w,
    const float* __restrict__ wx_b,
    const float* __restrict__ wc_w,
    const float* __restrict__ wc_b,
    float*       __restrict__ out)
{
    __shared__ __align__(16) float sW2T[64 * 64];     // transposed [f][g], 16 KB
    __shared__ __align__(16) char  uMem[48 * 68 * 4]; // hid[48][68] | sPacked[1024]+sWt[1024]
    __shared__ float sw3[64];
    __shared__ float sh[64], shsum[64], sbh1[64], sbh2[64];
    __shared__ int   sEnt1[32], sRel1[32];
    __shared__ float sScale1[32];
    __shared__ float sA[96];
    __shared__ float sWk[32], sWks[32], sE2[64];
    __shared__ float sDen[6];
    __shared__ float sAgg1[64], sAgg2[64], sV1[64], sV2[64];

    float* uHid    = reinterpret_cast<float*>(uMem);          // [48][68]
    int*   sPacked = reinterpret_cast<int*>(uMem);            // [1024]
    float* sWt     = reinterpret_cast<float*>(uMem + 4096);   // [1024]

    const int tid  = threadIdx.x;
    const int b    = blockIdx.x;
    const int lane = tid & 31;
    const int warp = tid >> 5;

    // ================= phase A: W2 transpose + indices + h =================
    for (int i = tid; i < 4096; i += 192)
        sW2T[(i & 63) * 64 + (i >> 6)] = att_w2[i];   // [f][g] <- [g][f]
    if (tid < 64) sw3[tid] = att_w3[tid];
    const int eidx = entity_idx[b];
    if (tid < 32) {
        int e1 = adj_entity[eidx * KN + tid];
        sEnt1[tid]   = e1;
        sRel1[tid]   = adj_relation[eidx * KN + tid];
        sScale1[tid] = g_scale[e1];
    }
    if (tid < 64) sh[tid] = E[eidx * 64 + tid] * g_scale[eidx];
    __syncthreads();

    // ====== phase B: hsum ==================================================
    if (tid < 64) {
        float s = 0.f;
        #pragma unroll 8
        for (int k = 0; k < 32; k++)
            s += sScale1[k] * E[sEnt1[k] * 64 + tid];
        shsum[tid] = s;
    }
    __syncthreads();

    // ====== phase C: bh1 = h @ w1h^T, bh2 = hsum @ w1h^T ===================
    if (tid < 128) {
        int f = tid & 63;
        const float*  src = (tid < 64) ? sh : shsum;
        const float4* w   = reinterpret_cast<const float4*>(att_w1 + f * 128);
        float a0 = 0.f, a1 = 0.f;
        #pragma unroll
        for (int e4 = 0; e4 < 16; e4 += 2) {
            float4 wv = w[e4], ww = w[e4 + 1];
            a0 += wv.x * src[e4*4]   + wv.y * src[e4*4+1]
                + wv.z * src[e4*4+2] + wv.w * src[e4*4+3];
            a1 += ww.x * src[e4*4+4] + ww.y * src[e4*4+5]
                + ww.z * src[e4*4+6] + ww.w * src[e4*4+7];
        }
        if (tid < 64) sbh1[f] = a0 + a1; else sbh2[f] = a0 + a1;
    }
    __syncthreads();

    // ====== stage 7: two 48-task halves; build hid, then GEMM-tile =========
    #pragma unroll 1
    for (int half = 0; half < 2; half++) {
        // build hid[lt][f] = relu(bh[f] + Rw[r][f]), lt = local task 0..47
        #pragma unroll
        for (int q = 0; q < 4; q++) {
            int e  = tid + q * 192;        // float4 unit, 0..767
            int lt = e >> 4, f4 = e & 15;
            int gt = half * 48 + lt;
            const float* bh = (gt < 32) ? sbh1 : sbh2;
            int r = (gt < 32) ? sRel1[gt] : (gt - 32);
            float4 rv = __ldg(reinterpret_cast<const float4*>(g_Rw + r * 64) + f4);
            float4 hv;
            hv.x = fmaxf(bh[f4*4]     + rv.x, 0.0f);
            hv.y = fmaxf(bh[f4*4 + 1] + rv.y, 0.0f);
            hv.z = fmaxf(bh[f4*4 + 2] + rv.z, 0.0f);
            hv.w = fmaxf(bh[f4*4 + 3] + rv.w, 0.0f);
            *reinterpret_cast<float4*>(&uHid[lt * 68 + f4 * 4]) = hv;
        }
        __syncthreads();

        // GEMM tile: thread = (task_tile 0..11) x (g4 0..15); 4 tasks x 4 g
        {
            const int task_tile = tid >> 4;
            const int g4 = tid & 15;
            const int tbase = task_tile * 4;
            unsigned long long acc[4][2];
            #pragma unroll
            for (int i = 0; i < 4; i++) { acc[i][0] = 0ull; acc[i][1] = 0ull; }

            #pragma unroll
            for (int f4 = 0; f4 < 16; f4++) {
                float4 hv0 = *reinterpret_cast<const float4*>(&uHid[(tbase)     * 68 + f4 * 4]);
                float4 hv1 = *reinterpret_cast<const float4*>(&uHid[(tbase + 1) * 68 + f4 * 4]);
                float4 hv2 = *reinterpret_cast<const float4*>(&uHid[(tbase + 2) * 68 + f4 * 4]);
                float4 hv3 = *reinterpret_cast<const float4*>(&uHid[(tbase + 3) * 68 + f4 * 4]);
                #pragma unroll
                for (int j = 0; j < 4; j++) {
                    ulonglong2 wv = *reinterpret_cast<const ulonglong2*>(
                        &sW2T[(f4 * 4 + j) * 64 + g4 * 4]);
                    float h0 = j == 0 ? hv0.x : j == 1 ? hv0.y : j == 2 ? hv0.z : hv0.w;
                    float h1 = j == 0 ? hv1.x : j == 1 ? hv1.y : j == 2 ? hv1.z : hv1.w;
                    float h2 = j == 0 ? hv2.x : j == 1 ? hv2.y : j == 2 ? hv2.z : hv2.w;
                    float h3 = j == 0 ? hv3.x : j == 1 ? hv3.y : j == 2 ? hv3.z : hv3.w;
                    unsigned long long b0 = pack2(h0, h0);
                    unsigned long long b1 = pack2(h1, h1);
                    unsigned long long b2 = pack2(h2, h2);
                    unsigned long long b3 = pack2(h3, h3);
                    acc[0][0] = fma2(b0, wv.x, acc[0][0]);
                    acc[0][1] = fma2(b0, wv.y, acc[0][1]);
                    acc[1][0] = fma2(b1, wv.x, acc[1][0]);
                    acc[1][1] = fma2(b1, wv.y, acc[1][1]);
                    acc[2][0] = fma2(b2, wv.x, acc[2][0]);
                    acc[2][1] = fma2(b2, wv.y, acc[2][1]);
                    acc[3][0] = fma2(b3, wv.x, acc[3][0]);
                    acc[3][1] = fma2(b3, wv.y, acc[3][1]);
                }
            }
            // relu + w3 dot (this thread's 4 g), then reduce across 16 g-lanes
            float w3a = sw3[g4 * 4], w3b = sw3[g4 * 4 + 1];
            float w3c = sw3[g4 * 4 + 2], w3d = sw3[g4 * 4 + 3];
            float dp[4];
            #pragma unroll
            for (int i = 0; i < 4; i++) {
                float2 p0 = unpack2(acc[i][0]);
                float2 p1 = unpack2(acc[i][1]);
                dp[i] = w3a * fmaxf(p0.x, 0.0f) + w3b * fmaxf(p0.y, 0.0f)
                      + w3c * fmaxf(p1.x, 0.0f) + w3d * fmaxf(p1.y, 0.0f);
            }
            #pragma unroll
            for (int o = 1; o < 16; o <<= 1) {
                #pragma unroll
                for (int i = 0; i < 4; i++)
                    dp[i] += __shfl_xor_sync(0xffffffffu, dp[i], o, 16);
            }
            if ((lane & 15) == 0) {
                int base = half * 48 + tbase;
                sA[base]     = dp[0];
                sA[base + 1] = dp[1];
                sA[base + 2] = dp[2];
                sA[base + 3] = dp[3];
            }
        }
        __syncthreads();   // hid consumed; safe to rebuild / re-alias
    }

    // ====== exp(sigmoid(a)) tables =========================================
    if (tid < 96) {
        float e = __expf(1.0f / (1.0f + __expf(-sA[tid])));
        if (tid < 32) { sWk[tid] = e; sWks[tid] = e * sScale1[tid]; }
        else          sE2[tid - 32] = e;
    }
    __syncthreads();

    // ====== pair staging + weights + denominator (uMem now pair buffers) ===
    {
        float esum = 0.f;
        for (int p = tid; p < 1024; p += 192) {
            int n1 = p >> 5, k = p & 31;
            int base = sEnt1[n1] * KN;
            int ei = adj_entity[base + k];
            int ri = adj_relation[base + k];
            float e = sE2[ri];
            esum += e;
            sPacked[p] = ei;
            sWt[p]     = e * g_scale[ei];
        }
        #pragma unroll
        for (int o = 16; o > 0; o >>= 1) esum += __shfl_xor_sync(0xffffffffu, esum, o);
        if (lane == 0) sDen[warp] = esum;
    }
    __syncthreads();

    // ====== gather (warps 0-3, 256 pairs each) | hop-1 agg (warps 4-5) =====
    if (warp < 4) {
        float accx = 0.f, accy = 0.f;
        const float2* E2 = reinterpret_cast<const float2*>(E);
        const int pbase = warp * 256;
        #pragma unroll 8
        for (int t = 0; t < 256; t++) {
            int  idx = sPacked[pbase + t];   // broadcast LDS
            float wt = sWt[pbase + t];       // broadcast LDS
            float2 v = E2[idx * 32 + lane];
            accx += wt * v.x;
            accy += wt * v.y;
        }
        sWt[pbase + lane * 2]     = accx;    // feature 2*lane
        sWt[pbase + lane * 2 + 1] = accy;    // feature 2*lane+1
    } else {
        const int t = tid - 128;             // 0..63
        float s1 = 0.f, acc = 0.f;
        #pragma unroll
        for (int k = 0; k < 32; k++) s1 += sWk[k];
        #pragma unroll 8
        for (int k = 0; k < 32; k++)
            acc += sWks[k] * E[sEnt1[k] * 64 + t];
        sAgg1[t] = acc / s1;
    }
    __syncthreads();

    // ====== hop-2 combine ==================================================
    if (tid < 64) {
        float s2 = sDen[0] + sDen[1] + sDen[2] + sDen[3] + sDen[4] + sDen[5];
        float acc = sWt[tid] + sWt[256 + tid] + sWt[512 + tid] + sWt[768 + tid];
        sAgg2[tid] = acc / s2;
    }
    __syncthreads();

    // ====== v1/v2 = leaky(agg @ wx_w^T + wx_b) =============================
    if (tid < 64) {
        const float4* w = reinterpret_cast<const float4*>(wx_w + tid * 64);
        float a1 = wx_b[tid], a2 = a1;
        #pragma unroll
        for (int e4 = 0; e4 < 16; e4++) {
            float4 wv = w[e4];
            a1 += wv.x * sAgg1[e4*4]   + wv.y * sAgg1[e4*4+1]
                + wv.z * sAgg1[e4*4+2] + wv.w * sAgg1[e4*4+3];
            a2 += wv.x * sAgg2[e4*4]   + wv.y * sAgg2[e4*4+1]
                + wv.z * sAgg2[e4*4+2] + wv.w * sAgg2[e4*4+3];
        }
        sV1[tid] = (a1 >= 0.f) ? a1 : SLOPE * a1;
        sV2[tid] = (a2 >= 0.f) ? a2 : SLOPE * a2;
    }
    __syncthreads();

    // ====== emb1/emb2 = leaky([x, v] @ wc_w^T + wc_b) + h out ==============
    if (tid < 64) {
        const float4* w = reinterpret_cast<const float4*>(wc_w + tid * 128);
        float a1 = wc_b[tid], a2 = a1;
        #pragma unroll
        for (int e4 = 0; e4 < 16; e4++) {
            float4 wv = w[e4];
            a1 += wv.x * sh[e4*4]      + wv.y * sh[e4*4+1]
                + wv.z * sh[e4*4+2]    + wv.w * sh[e4*4+3];
            a2 += wv.x * shsum[e4*4]   + wv.y * shsum[e4*4+1]
                + wv.z * shsum[e4*4+2] + wv.w * shsum[e4*4+3];
        }
        #pragma unroll
        for (int e4 = 0; e4 < 16; e4++) {
            float4 wv = w[16 + e4];
            a1 += wv.x * sV1[e4*4]   + wv.y * sV1[e4*4+1]
                + wv.z * sV1[e4*4+2] + wv.w * sV1[e4*4+3];
            a2 += wv.x * sV2[e4*4]   + wv.y * sV2[e4*4+1]
                + wv.z * sV2[e4*4+2] + wv.w * sV2[e4*4+3];
        }
        out[b * 192 + 64 + tid]  = (a1 >= 0.f) ? a1 : SLOPE * a1;
        out[b * 192 + tid]       = (a2 >= 0.f) ? a2 : SLOPE * a2;
        out[b * 192 + 128 + tid] = sh[tid];
    }
}

extern "C" void kernel_launch(void* const* d_in, const int* in_sizes, int n_in,
                              void* d_out, int out_size) {
    const int*   entity_idx   = (const int*)  d_in[0];
    const int*   adj_entity   = (const int*)  d_in[1];
    const int*   adj_relation = (const int*)  d_in[2];
    const float* E            = (const float*)d_in[3];
    const float* R            = (const float*)d_in[4];
    const float* att_w1       = (const float*)d_in[5];
    const float* att_w2       = (const float*)d_in[6];
    const float* att_w3       = (const float*)d_in[7];
    const float* wx_w         = (const float*)d_in[8];
    const float* wx_b         = (const float*)d_in[9];
    const float* wc_w         = (const float*)d_in[10];
    const float* wc_b         = (const float*)d_in[11];
    float* out = (float*)d_out;

    prep_kernel<<<798, 256>>>(E, R, att_w1);
    kgan_main_kernel<<<BSZ, 192>>>(entity_idx, adj_entity, adj_relation, E,
                                   att_w1, att_w2, att_w3,
                                   wx_w, wx_b, wc_w, wc_b, out);
}

// round 13
// speedup vs baseline: 1.3641x; 1.1295x over previous
#include <cuda_runtime.h>
#include <math.h>

#define N_ENT 100000
#define N_REL 64
#define EDIM  64
#define KN    32
#define BSZ   1024
#define SLOPE 0.2f

__device__ float g_scale[N_ENT];
__device__ __align__(16) float g_Rw[N_REL * EDIM];  // [r][f] rows

// ---- packed fp32x2 helpers ----
__device__ __forceinline__ unsigned long long fma2(unsigned long long a,
                                                   unsigned long long b,
                                                   unsigned long long c) {
    unsigned long long d;
    asm("fma.rn.f32x2 %0, %1, %2, %3;" : "=l"(d) : "l"(a), "l"(b), "l"(c));
    return d;
}
__device__ __forceinline__ unsigned long long pack2(float lo, float hi) {
    unsigned long long d;
    asm("mov.b64 %0, {%1, %2};" : "=l"(d) : "f"(lo), "f"(hi));
    return d;
}
__device__ __forceinline__ float2 unpack2(unsigned long long v) {
    float2 r;
    asm("mov.b64 {%0, %1}, %2;" : "=f"(r.x), "=f"(r.y) : "l"(v));
    return r;
}

// ---------------------------------------------------------------------------
// Prep: per-row E scale (782 blocks) + Rw slices (16 blocks, [r][f] out)
// ---------------------------------------------------------------------------
__global__ void prep_kernel(const float* __restrict__ E,
                            const float* __restrict__ R,
                            const float* __restrict__ att_w1) {
    const int tid = threadIdx.x;  // 256
    if (blockIdx.x < 782) {
        const int row  = blockIdx.x * 128 + (tid >> 1);
        const int part = tid & 1;
        if (row >= N_ENT) return;
        const float4* Ev = reinterpret_cast<const float4*>(E + row * 64) + part * 8;
        float ss = 0.f;
        #pragma unroll
        for (int i = 0; i < 8; i++) {
            float4 v = Ev[i];
            ss += v.x*v.x + v.y*v.y + v.z*v.z + v.w*v.w;
        }
        ss += __shfl_xor_sync(0xffffffffu, ss, 1, 2);
        if (part == 0) {
            float n = sqrtf(ss);
            g_scale[row] = (n > 1.0f) ? (1.0f / (n + 1e-7f)) : 1.0f;
        }
        return;
    }
    __shared__ __align__(16) float sRn[N_REL * EDIM];
    __shared__ float sScale[N_REL];
    const int slice = blockIdx.x - 782;
    for (int i = tid; i < N_REL * EDIM; i += 256) sRn[i] = R[i];
    __syncthreads();
    if (tid < N_REL) {
        const float4* rv = reinterpret_cast<const float4*>(sRn + tid * EDIM);
        float ss = 0.f;
        #pragma unroll
        for (int e4 = 0; e4 < 16; e4++) {
            float4 v = rv[e4];
            ss += v.x*v.x + v.y*v.y + v.z*v.z + v.w*v.w;
        }
        float n = sqrtf(ss);
        sScale[tid] = (n > 1.0f) ? (1.0f / (n + 1e-7f)) : 1.0f;
    }
    __syncthreads();
    for (int i = tid; i < N_REL * EDIM; i += 256) sRn[i] *= sScale[i >> 6];
    __syncthreads();
    {
        int i = slice * 256 + tid;       // g_Rw[r][f]
        int r = i >> 6, f = i & 63;
        const float4* w  = reinterpret_cast<const float4*>(att_w1 + f * 128 + 64);
        const float4* rn = reinterpret_cast<const float4*>(sRn + r * 64);
        float a0 = 0.f, a1 = 0.f;
        #pragma unroll
        for (int e4 = 0; e4 < 16; e4 += 2) {
            float4 rv = rn[e4],     wv = w[e4];
            float4 rw = rn[e4 + 1], ww = w[e4 + 1];
            a0 += rv.x*wv.x + rv.y*wv.y + rv.z*wv.z + rv.w*wv.w;
            a1 += rw.x*ww.x + rw.y*ww.y + rw.z*ww.z + rw.w*ww.w;
        }
        g_Rw[i] = a0 + a1;
    }
}

// ---------------------------------------------------------------------------
// Main: one block per batch element, 128 threads, 7 blocks/SM.
// Exactly the R7 structure; deltas: Rw row float4 loads, gather MLP 16.
// ---------------------------------------------------------------------------
__global__ __launch_bounds__(128, 7) void kgan_main_kernel(
    const int*   __restrict__ entity_idx,
    const int*   __restrict__ adj_entity,
    const int*   __restrict__ adj_relation,
    const float* __restrict__ E,
    const float* __restrict__ att_w1,
    const float* __restrict__ att_w2,
    const float* __restrict__ att_w3,
    const float* __restrict__ wx_w,
    const float* __restrict__ wx_b,
    const float* __restrict__ wc_w,
    const float* __restrict__ wc_b,
    float*       __restrict__ out)
{
    __shared__ __align__(16) float sW2[64 * 64];    // permuted float4 slots: g*16 + j*2 + fh
    __shared__ __align__(16) int   sPacked[1024];   // ei | (ri<<17)
    __shared__ __align__(16) float sWt[1024];       // pair weights; warp tails reused for partials
    __shared__ float sw3[64];
    __shared__ float sh[64], shsum[64], sbh1[64], sbh2[64];
    __shared__ int   sEnt1[32], sRel1[32];
    __shared__ float sScale1[32];
    __shared__ float sA[96];
    __shared__ float sWk[32], sWks[32], sE2[64];
    __shared__ float sDen[4];
    __shared__ float sAgg1[64], sAgg2[64], sV1[64], sV2[64];

    const int tid  = threadIdx.x;
    const int b    = blockIdx.x;
    const int lane = tid & 31;
    const int warp = tid >> 5;

    // ================= phase A: W2 table + level-1 indices =================
    {
        const float4* Ws = reinterpret_cast<const float4*>(att_w2);
        float4*       Wd = reinterpret_cast<float4*>(sW2);
        #pragma unroll
        for (int q = 0; q < 8; q++) {
            int i = tid + q * 128;
            int g = i >> 4, i4 = i & 15;
            Wd[g * 16 + ((i4 & 7) << 1) + (i4 >> 3)] = Ws[i];  // interleave f-halves
        }
    }
    if (tid < 64) sw3[tid] = att_w3[tid];
    const int eidx = entity_idx[b];
    if (tid < 32) {
        int e1 = adj_entity[eidx * KN + tid];
        sEnt1[tid]   = e1;
        sRel1[tid]   = adj_relation[eidx * KN + tid];
        sScale1[tid] = g_scale[e1];
    }
    if (tid < 64) sh[tid] = E[eidx * 64 + tid] * g_scale[eidx];
    __syncthreads();

    // ====== phase B: stage hop-2 adjacency (packed) + hsum =================
    #pragma unroll
    for (int q = 0; q < 8; q++) {
        int p  = tid + q * 128;
        int n1 = p >> 5, k = p & 31;
        int base = sEnt1[n1] * KN;
        int ei = adj_entity[base + k];
        int ri = adj_relation[base + k];
        sPacked[p] = ei | (ri << 17);
    }
    if (tid < 64) {
        float s = 0.f;
        #pragma unroll 8
        for (int k = 0; k < 32; k++)
            s += sScale1[k] * E[sEnt1[k] * 64 + tid];
        shsum[tid] = s;
    }
    __syncthreads();

    // ====== phase C: bh1 = h @ w1h^T, bh2 = hsum @ w1h^T (128 threads) =====
    {
        int f = tid & 63;
        const float*  src = (tid < 64) ? sh : shsum;
        const float4* w   = reinterpret_cast<const float4*>(att_w1 + f * 128);
        float a0 = 0.f, a1 = 0.f;
        #pragma unroll
        for (int e4 = 0; e4 < 16; e4 += 2) {
            float4 wv = w[e4], ww = w[e4 + 1];
            a0 += wv.x * src[e4*4]   + wv.y * src[e4*4+1]
                + wv.z * src[e4*4+2] + wv.w * src[e4*4+3];
            a1 += ww.x * src[e4*4+4] + ww.y * src[e4*4+5]
                + ww.z * src[e4*4+6] + ww.w * src[e4*4+7];
        }
        if (tid < 64) sbh1[f] = a0 + a1; else sbh2[f] = a0 + a1;
    }
    __syncthreads();

    // ====== stage 7: 96 tasks x 2 f-halves = 192 thread-tasks, 2 passes ====
    #pragma unroll
    for (int pass = 0; pass < 2; pass++) {
        int tt = tid + pass * 128;
        if (tt < 192) {
            const int task = tt >> 1;
            const int fh   = tt & 1;
            const float* bh = (task < 32) ? sbh1 : sbh2;
            const int    r  = (task < 32) ? sRel1[task] : (task - 32);

            // Rw row r contiguous: 4 x LDG.128 against L1-resident 16 KB table
            const float4* rw = reinterpret_cast<const float4*>(g_Rw + r * 64) + fh * 8;
            unsigned long long hidp[16];
            #pragma unroll
            for (int m4 = 0; m4 < 8; m4++) {
                float4 rv = __ldg(&rw[m4]);
                int f = fh * 32 + m4 * 4;
                float h0 = fmaxf(bh[f]     + rv.x, 0.0f);
                float h1 = fmaxf(bh[f + 1] + rv.y, 0.0f);
                float h2 = fmaxf(bh[f + 2] + rv.z, 0.0f);
                float h3 = fmaxf(bh[f + 3] + rv.w, 0.0f);
                hidp[m4 * 2]     = pack2(h0, h1);
                hidp[m4 * 2 + 1] = pack2(h2, h3);
            }
            const ulonglong2* w2 = reinterpret_cast<const ulonglong2*>(sW2);
            float a = 0.0f;
            #pragma unroll
            for (int gb = 0; gb < 64; gb += 8) {
                float dp[8];
                #pragma unroll
                for (int u = 0; u < 8; u++) {
                    const int g = gb + u;
                    unsigned long long dpp = 0ull;
                    #pragma unroll
                    for (int j = 0; j < 8; j++) {
                        ulonglong2 wv = w2[g * 16 + j * 2 + fh];
                        dpp = fma2(wv.x, hidp[j * 2],     dpp);
                        dpp = fma2(wv.y, hidp[j * 2 + 1], dpp);
                    }
                    float2 dd = unpack2(dpp);
                    dp[u] = dd.x + dd.y;
                }
                #pragma unroll
                for (int u = 0; u < 8; u++)
                    dp[u] += __shfl_xor_sync(0xffffffffu, dp[u], 1);
                #pragma unroll
                for (int u = 0; u < 8; u++)
                    a += sw3[gb + u] * fmaxf(dp[u], 0.0f);
            }
            if (fh == 0) sA[task] = a;
        }
    }
    __syncthreads();

    // ====== exp(sigmoid(a)) tables =========================================
    if (tid < 96) {
        float e = __expf(1.0f / (1.0f + __expf(-sA[tid])));
        if (tid < 32) { sWk[tid] = e; sWks[tid] = e * sScale1[tid]; }
        else          sE2[tid - 32] = e;
    }
    __syncthreads();

    // ====== hop-2 pair weights + denominator ===============================
    float esum = 0.f;
    #pragma unroll
    for (int q = 0; q < 8; q++) {
        int p  = tid + q * 128;
        int pk = sPacked[p];
        int ei = pk & 0x1FFFF;
        float e = sE2[pk >> 17];
        esum  += e;
        sWt[p] = e * g_scale[ei];
    }
    #pragma unroll
    for (int o = 16; o > 0; o >>= 1) esum += __shfl_xor_sync(0xffffffffu, esum, o);
    if (lane == 0) sDen[warp] = esum;
    __syncthreads();

    // ====== hop-2 gather: warp = 256 pairs, 2-pair iter, MLP 16 ============
    {
        float ax0 = 0.f, ay0 = 0.f, ax1 = 0.f, ay1 = 0.f;
        const float2* E2 = reinterpret_cast<const float2*>(E);
        const int pbase = warp * 256;
        #pragma unroll 8
        for (int t = 0; t < 256; t += 2) {
            int   pk0 = sPacked[pbase + t];
            int   pk1 = sPacked[pbase + t + 1];
            float w0  = sWt[pbase + t];
            float w1  = sWt[pbase + t + 1];
            float2 v0 = E2[(pk0 & 0x1FFFF) * 32 + lane];
            float2 v1 = E2[(pk1 & 0x1FFFF) * 32 + lane];
            ax0 += w0 * v0.x; ay0 += w0 * v0.y;
            ax1 += w1 * v1.x; ay1 += w1 * v1.y;
        }
        // partials into this warp's own fully-consumed sWt segment
        sWt[pbase + lane * 2]     = ax0 + ax1;   // feature 2*lane
        sWt[pbase + lane * 2 + 1] = ay0 + ay1;   // feature 2*lane+1
    }
    __syncthreads();

    // ====== hop-1 agg (tid<64) + hop-2 combine (tid in [64,128)) ===========
    if (tid < 64) {
        float s1 = 0.f, acc = 0.f;
        #pragma unroll
        for (int k = 0; k < 32; k++) s1 += sWk[k];
        #pragma unroll 8
        for (int k = 0; k < 32; k++)
            acc += sWks[k] * E[sEnt1[k] * 64 + tid];
        sAgg1[tid] = acc / s1;
    } else {
        int f = tid - 64;
        float s2 = sDen[0] + sDen[1] + sDen[2] + sDen[3];
        float acc = sWt[f] + sWt[256 + f] + sWt[512 + f] + sWt[768 + f];
        sAgg2[f] = acc / s2;
    }
    __syncthreads();

    // ====== v1/v2 = leaky(agg @ wx_w^T + wx_b) =============================
    if (tid < 64) {
        const float4* w = reinterpret_cast<const float4*>(wx_w + tid * 64);
        float a1 = wx_b[tid], a2 = a1;
        #pragma unroll
        for (int e4 = 0; e4 < 16; e4++) {
            float4 wv = w[e4];
            a1 += wv.x * sAgg1[e4*4]   + wv.y * sAgg1[e4*4+1]
                + wv.z * sAgg1[e4*4+2] + wv.w * sAgg1[e4*4+3];
            a2 += wv.x * sAgg2[e4*4]   + wv.y * sAgg2[e4*4+1]
                + wv.z * sAgg2[e4*4+2] + wv.w * sAgg2[e4*4+3];
        }
        sV1[tid] = (a1 >= 0.f) ? a1 : SLOPE * a1;
        sV2[tid] = (a2 >= 0.f) ? a2 : SLOPE * a2;
    }
    __syncthreads();

    // ====== emb1/emb2 = leaky([x, v] @ wc_w^T + wc_b) + h out ==============
    if (tid < 64) {
        const float4* w = reinterpret_cast<const float4*>(wc_w + tid * 128);
        float a1 = wc_b[tid], a2 = a1;
        #pragma unroll
        for (int e4 = 0; e4 < 16; e4++) {
            float4 wv = w[e4];
            a1 += wv.x * sh[e4*4]      + wv.y * sh[e4*4+1]
                + wv.z * sh[e4*4+2]    + wv.w * sh[e4*4+3];
            a2 += wv.x * shsum[e4*4]   + wv.y * shsum[e4*4+1]
                + wv.z * shsum[e4*4+2] + wv.w * shsum[e4*4+3];
        }
        #pragma unroll
        for (int e4 = 0; e4 < 16; e4++) {
            float4 wv = w[16 + e4];
            a1 += wv.x * sV1[e4*4]   + wv.y * sV1[e4*4+1]
                + wv.z * sV1[e4*4+2] + wv.w * sV1[e4*4+3];
            a2 += wv.x * sV2[e4*4]   + wv.y * sV2[e4*4+1]
                + wv.z * sV2[e4*4+2] + wv.w * sV2[e4*4+3];
        }
        out[b * 192 + 64 + tid]  = (a1 >= 0.f) ? a1 : SLOPE * a1;
        out[b * 192 + tid]       = (a2 >= 0.f) ? a2 : SLOPE * a2;
        out[b * 192 + 128 + tid] = sh[tid];
    }
}

extern "C" void kernel_launch(void* const* d_in, const int* in_sizes, int n_in,
                              void* d_out, int out_size) {
    const int*   entity_idx   = (const int*)  d_in[0];
    const int*   adj_entity   = (const int*)  d_in[1];
    const int*   adj_relation = (const int*)  d_in[2];
    const float* E            = (const float*)d_in[3];
    const float* R            = (const float*)d_in[4];
    const float* att_w1       = (const float*)d_in[5];
    const float* att_w2       = (const float*)d_in[6];
    const float* att_w3       = (const float*)d_in[7];
    const float* wx_w         = (const float*)d_in[8];
    const float* wx_b         = (const float*)d_in[9];
    const float* wc_w         = (const float*)d_in[10];
    const float* wc_b         = (const float*)d_in[11];
    float* out = (float*)d_out;

    prep_kernel<<<798, 256>>>(E, R, att_w1);
    kgan_main_kernel<<<BSZ, 128>>>(entity_idx, adj_entity, adj_relation, E,
                                   att_w1, att_w2, att_w3,
                                   wx_w, wx_b, wc_w, wc_b, out);
}